// round 2
// baseline (speedup 1.0000x reference)
#include <cuda_runtime.h>
#include <math.h>

#define BATCH 32
#define NTOK 197
#define DIM 384
#define HEADS 12
#define HD 32
#define HID 36
#define MLPH 1536
#define MTOK (BATCH*NTOK)           // 6304
#define HW (NTOK*NTOK)              // 38809
#define BH (BATCH*HEADS)            // 384
#define BHID (BATCH*HID)            // 1152
#define CNT ((double)(BATCH)*(double)HW)  // 1241888
#define EPSF 1e-5f
#define SQF 0.4204482076268573f     // 32^-0.25

// ---------------- scratch (device globals; no allocation allowed) ----------
__device__ float g_h[MTOK*DIM];
__device__ float g_q[BH*NTOK*HD];
__device__ float g_k[BH*NTOK*HD];
__device__ float g_v[BH*NTOK*HD];
__device__ float g_attn0[(size_t)BH*HW];
__device__ float g_a1[(size_t)BHID*HW];
__device__ float g_a2[(size_t)BHID*HW];
__device__ float g_a3[(size_t)BH*HW];
__device__ float g_attnout[MTOK*DIM];
__device__ float g_x1[MTOK*DIM];
__device__ float g_h2[MTOK*DIM];
__device__ float g_mlp[(size_t)MTOK*MLPH];
__device__ double g_stats[204];   // s1[36] ss1[36] s2[36] ss2[36] s3[12] ss3[12] s0[12] ss0[12] sx[12]
__device__ float g_par1[72];      // bn1 scale, shift
__device__ float g_par2[72];      // bn2 scale, shift
__device__ float g_abc[36];       // ca[12] cb[12] cc[12]

// ---------------- zero stats ----------------
__global__ void zero_stats_kernel() {
    int t = threadIdx.x;
    if (t < 204) g_stats[t] = 0.0;
}

// ---------------- layernorm(x*0.5) ----------------
// sel=0: src=param x      -> g_h
// sel=1: src=g_x1         -> g_h2
__global__ __launch_bounds__(128) void ln_kernel(const float* __restrict__ src_in,
                                                 const float* __restrict__ g,
                                                 const float* __restrict__ b,
                                                 int sel) {
    const float* src = sel ? g_x1 : src_in;
    float* dst = sel ? g_h2 : g_h;
    int tok = blockIdx.x;
    const float* xp = src + (size_t)tok * DIM;
    float* yp = dst + (size_t)tok * DIM;
    int tid = threadIdx.x;
    float v[3];
    float s = 0.f, ss = 0.f;
#pragma unroll
    for (int i = 0; i < 3; i++) {
        float t = 0.5f * xp[tid + i * 128];
        v[i] = t; s += t; ss += t * t;
    }
    // reduce
    __shared__ float rs[4], rss[4];
#pragma unroll
    for (int off = 16; off; off >>= 1) {
        s  += __shfl_xor_sync(0xffffffffu, s, off);
        ss += __shfl_xor_sync(0xffffffffu, ss, off);
    }
    int w = tid >> 5, lane = tid & 31;
    if (lane == 0) { rs[w] = s; rss[w] = ss; }
    __syncthreads();
    float S = rs[0] + rs[1] + rs[2] + rs[3];
    float SS = rss[0] + rss[1] + rss[2] + rss[3];
    float mean = S * (1.0f / DIM);
    float var = SS * (1.0f / DIM) - mean * mean;
    float inv = rsqrtf(var + EPSF);
#pragma unroll
    for (int i = 0; i < 3; i++) {
        int j = tid + i * 128;
        yp[j] = (v[i] - mean) * inv * g[j] + b[j];
    }
}

// ---------------- generic tiled GEMM: C[m,n] = sum_k A[m,k]*W[n,k] -------
// EPI 1: A=g_h,     scatter to q/k/v with SQF scaling
// EPI 2: A=g_attnout, g_x1 = resid + 2*(acc+bias)
// EPI 3: A=g_h2,    g_mlp = gelu(acc+bias)
// EPI 4: A=g_mlp,   C = g_x1 + 2*(acc+bias)*scalev
template <int EPI>
__global__ __launch_bounds__(256) void gemm_kernel(const float* __restrict__ W,
                                                   float* __restrict__ C,
                                                   int M, int Nn, int K,
                                                   const float* __restrict__ bias,
                                                   const float* __restrict__ resid,
                                                   const float* __restrict__ scalev) {
    const float* A = (EPI == 1) ? g_h : (EPI == 2) ? g_attnout : (EPI == 3) ? g_h2 : g_mlp;
    __shared__ float As[16][68];
    __shared__ float Ws[16][68];
    int tid = threadIdx.x;
    int m0 = blockIdx.y * 64, n0 = blockIdx.x * 64;
    int tx = tid & 15, ty = tid >> 4;
    float acc[4][4];
#pragma unroll
    for (int i = 0; i < 4; i++)
#pragma unroll
        for (int j = 0; j < 4; j++) acc[i][j] = 0.f;

    for (int k0 = 0; k0 < K; k0 += 16) {
#pragma unroll
        for (int i = 0; i < 4; i++) {
            int idx = tid + i * 256;
            int rr = idx >> 4, kk = idx & 15;
            int gm = m0 + rr;
            As[kk][rr] = (gm < M) ? A[(size_t)gm * K + k0 + kk] : 0.f;
            Ws[kk][rr] = W[(size_t)(n0 + rr) * K + k0 + kk];
        }
        __syncthreads();
#pragma unroll
        for (int kk = 0; kk < 16; kk++) {
            float4 av = *reinterpret_cast<const float4*>(&As[kk][ty * 4]);
            float4 bv = *reinterpret_cast<const float4*>(&Ws[kk][tx * 4]);
            float a[4] = {av.x, av.y, av.z, av.w};
            float b[4] = {bv.x, bv.y, bv.z, bv.w};
#pragma unroll
            for (int i = 0; i < 4; i++)
#pragma unroll
                for (int j = 0; j < 4; j++) acc[i][j] = fmaf(a[i], b[j], acc[i][j]);
        }
        __syncthreads();
    }

#pragma unroll
    for (int i = 0; i < 4; i++) {
        int m = m0 + ty * 4 + i;
        if (m >= M) continue;
#pragma unroll
        for (int j = 0; j < 4; j++) {
            int n = n0 + tx * 4 + j;
            float v = acc[i][j];
            if (EPI == 1) {
                int b_ = m / NTOK, ntok = m - b_ * NTOK;
                int s = n / DIM, rem = n - s * DIM;
                int hh = rem >> 5, d = rem & 31;
                float val = v * ((s < 2) ? SQF : 1.f);
                size_t dst = (((size_t)(b_ * HEADS + hh) * NTOK) + ntok) * HD + d;
                if (s == 0) g_q[dst] = val;
                else if (s == 1) g_k[dst] = val;
                else g_v[dst] = val;
            } else if (EPI == 2) {
                size_t idx = (size_t)m * DIM + n;
                g_x1[idx] = resid[idx] + 2.f * (v + bias[n]);
            } else if (EPI == 3) {
                float t = v + bias[n];
                g_mlp[(size_t)m * Nn + n] = t * 0.5f * (1.f + erff(t * 0.70710678118654752f));
            } else { // EPI == 4
                size_t idx = (size_t)m * DIM + n;
                C[idx] = g_x1[idx] + 2.f * (v + bias[n]) * scalev[n];
            }
        }
    }
}

// ---------------- QK^T + softmax, per (b,h) ----------------
__global__ __launch_bounds__(256) void qk_softmax_kernel() {
    int bh = blockIdx.x;
    __shared__ float Ks[NTOK * 33];
    __shared__ float Qs[8][32];
    int tid = threadIdx.x;
    size_t kbase = (size_t)bh * NTOK * HD;
    for (int idx = tid; idx < NTOK * HD; idx += 256) {
        int m = idx >> 5, d = idx & 31;
        Ks[m * 33 + d] = g_k[kbase + idx];
    }
    __syncthreads();
    int w = tid >> 5, lane = tid & 31;
    for (int n = w; n < NTOK; n += 8) {
        Qs[w][lane] = g_q[kbase + (size_t)n * HD + lane];
        __syncwarp();
        float l[7];
        float mx = -1e30f;
#pragma unroll
        for (int c = 0; c < 7; c++) {
            int m = lane + c * 32;
            float a = -1e30f;
            if (m < NTOK) {
                a = 0.f;
#pragma unroll
                for (int d = 0; d < 32; d++) a = fmaf(Qs[w][d], Ks[m * 33 + d], a);
            }
            l[c] = a;
            mx = fmaxf(mx, a);
        }
#pragma unroll
        for (int off = 16; off; off >>= 1) mx = fmaxf(mx, __shfl_xor_sync(0xffffffffu, mx, off));
        float sum = 0.f;
#pragma unroll
        for (int c = 0; c < 7; c++) {
            l[c] = __expf(l[c] - mx);
            sum += l[c];
        }
#pragma unroll
        for (int off = 16; off; off >>= 1) sum += __shfl_xor_sync(0xffffffffu, sum, off);
        float inv = 1.f / sum;
        size_t obase = (size_t)bh * HW + (size_t)n * NTOK;
#pragma unroll
        for (int c = 0; c < 7; c++) {
            int m = lane + c * 32;
            if (m < NTOK) g_attn0[obase + m] = l[c] * inv;
        }
        __syncwarp();
    }
}

// ---------------- expand 1x1: a1 = Wexp(36x12) @ attn0; + bn1 moments ----
__global__ __launch_bounds__(288) void expand_kernel(const float* __restrict__ wexp) {
    int b = blockIdx.x;
    int grp = blockIdx.y; // 0..7
    int tid = threadIdx.x;
    int co = tid >> 3, j = tid & 7;
    float w[12];
#pragma unroll
    for (int i = 0; i < 12; i++) w[i] = wexp[co * 12 + i];
    __shared__ float insm[12 * 512];
    __shared__ float reds[288], redss[288];
    float s = 0.f, ss = 0.f;
    for (int tt = grp; tt < 76; tt += 8) {
        int hw0 = tt * 512;
        __syncthreads();
        for (int idx = tid; idx < 12 * 512; idx += 288) {
            int ci = idx >> 9, p = idx & 511;
            int hw = hw0 + p;
            insm[idx] = (hw < HW) ? g_attn0[(size_t)(b * HEADS + ci) * HW + hw] : 0.f;
        }
        __syncthreads();
        for (int p = j; p < 512; p += 8) {
            int hw = hw0 + p;
            if (hw < HW) {
                float acc = 0.f;
#pragma unroll
                for (int i = 0; i < 12; i++) acc = fmaf(w[i], insm[i * 512 + p], acc);
                g_a1[(size_t)(b * HID + co) * HW + hw] = acc;
                s += acc; ss += acc * acc;
            }
        }
    }
    reds[tid] = s; redss[tid] = ss;
    __syncthreads();
    if (j == 0) {
        float ts = 0.f, tss = 0.f;
#pragma unroll
        for (int q = 0; q < 8; q++) { ts += reds[co * 8 + q]; tss += redss[co * 8 + q]; }
        atomicAdd(&g_stats[co], (double)ts);
        atomicAdd(&g_stats[36 + co], (double)tss);
    }
}

// ---------------- bn finalize (bn1/bn2) ----------------
__global__ void bn_fin_kernel(const float* __restrict__ g, const float* __restrict__ b,
                              int soff, int ssoff, int which) {
    int c = threadIdx.x;
    if (c < HID) {
        double mean = g_stats[soff + c] / CNT;
        double var = g_stats[ssoff + c] / CNT - mean * mean;
        double sc = (double)g[c] / sqrt(var + 1e-5);
        float* par = which ? g_par2 : g_par1;
        par[c] = (float)sc;
        par[36 + c] = (float)((double)b[c] - mean * sc);
    }
}

// ---------------- depthwise 3x3 SAME on relu6(bn1(a1)); + bn2 moments ----
__global__ __launch_bounds__(256) void dw_kernel(const float* __restrict__ dww) {
    int bc = blockIdx.x;
    int b = bc / HID, c = bc - b * HID;
    int y0 = blockIdx.y * 16;
    float sc = g_par1[c], sh = g_par1[36 + c];
    float w9[9];
#pragma unroll
    for (int i = 0; i < 9; i++) w9[i] = dww[c * 9 + i];
    __shared__ float sm[18 * NTOK];
    int tid = threadIdx.x;
    const float* src = g_a1 + (size_t)bc * HW;
    for (int idx = tid; idx < 18 * NTOK; idx += 256) {
        int r = idx / NTOK, xcol = idx - r * NTOK;
        int y = y0 - 1 + r;
        float v = 0.f;
        if (y >= 0 && y < NTOK) {
            v = src[(size_t)y * NTOK + xcol] * sc + sh;
            v = fminf(fmaxf(v, 0.f), 6.f);
        }
        sm[idx] = v;
    }
    __syncthreads();
    float s = 0.f, ss = 0.f;
    float* dst = g_a2 + (size_t)bc * HW;
    for (int idx = tid; idx < 16 * NTOK; idx += 256) {
        int yy = idx / NTOK, xcol = idx - yy * NTOK;
        int y = y0 + yy;
        if (y < NTOK) {
            float acc = 0.f;
#pragma unroll
            for (int ky = 0; ky < 3; ky++) {
                const float* row = sm + (yy + ky) * NTOK;
                if (xcol > 0) acc = fmaf(w9[ky * 3 + 0], row[xcol - 1], acc);
                acc = fmaf(w9[ky * 3 + 1], row[xcol], acc);
                if (xcol < NTOK - 1) acc = fmaf(w9[ky * 3 + 2], row[xcol + 1], acc);
            }
            dst[(size_t)y * NTOK + xcol] = acc;
            s += acc; ss += acc * acc;
        }
    }
    // block reduce
    __shared__ float rs[8], rss[8];
#pragma unroll
    for (int off = 16; off; off >>= 1) {
        s  += __shfl_xor_sync(0xffffffffu, s, off);
        ss += __shfl_xor_sync(0xffffffffu, ss, off);
    }
    int w = tid >> 5, lane = tid & 31;
    if (lane == 0) { rs[w] = s; rss[w] = ss; }
    __syncthreads();
    if (tid == 0) {
        float ts = 0.f, tss = 0.f;
#pragma unroll
        for (int q = 0; q < 8; q++) { ts += rs[q]; tss += rss[q]; }
        atomicAdd(&g_stats[72 + c], (double)ts);
        atomicAdd(&g_stats[108 + c], (double)tss);
    }
}

// ---------------- project 1x1: a3 = Wpro(12x36) @ relu6(bn2(a2)); 5 moments
__global__ __launch_bounds__(192) void project_kernel(const float* __restrict__ wpro) {
    int b = blockIdx.x;
    int grp = blockIdx.y; // 0..7
    int tid = threadIdx.x;
    int co = tid >> 4, j = tid & 15;
    float w[36];
#pragma unroll
    for (int i = 0; i < 36; i++) w[i] = wpro[co * 36 + i];
    __shared__ float insm[36 * 256];
    __shared__ float red[192 * 5];
    float s3 = 0.f, ss3 = 0.f, s0 = 0.f, ss0 = 0.f, sx = 0.f;
    for (int tt = grp; tt < 152; tt += 8) {
        int hw0 = tt * 256;
        __syncthreads();
        for (int idx = tid; idx < 36 * 256; idx += 192) {
            int ci = idx >> 8, p = idx & 255;
            int hw = hw0 + p;
            float v = 0.f;
            if (hw < HW) {
                v = g_a2[(size_t)(b * HID + ci) * HW + hw] * g_par2[ci] + g_par2[36 + ci];
                v = fminf(fmaxf(v, 0.f), 6.f);
            }
            insm[idx] = v;
        }
        __syncthreads();
        for (int p = j; p < 256; p += 16) {
            int hw = hw0 + p;
            if (hw < HW) {
                float acc = 0.f;
#pragma unroll
                for (int i = 0; i < 36; i++) acc = fmaf(w[i], insm[i * 256 + p], acc);
                size_t oidx = (size_t)(b * HEADS + co) * HW + hw;
                g_a3[oidx] = acc;
                float a0 = g_attn0[oidx];
                s3 += acc; ss3 += acc * acc;
                s0 += a0;  ss0 += a0 * a0;
                sx += acc * a0;
            }
        }
    }
    red[tid] = s3; red[192 + tid] = ss3; red[384 + tid] = s0; red[576 + tid] = ss0; red[768 + tid] = sx;
    __syncthreads();
    if (j == 0) {
        float t0 = 0.f, t1 = 0.f, t2 = 0.f, t3 = 0.f, t4 = 0.f;
#pragma unroll
        for (int q = 0; q < 16; q++) {
            int ii = co * 16 + q;
            t0 += red[ii]; t1 += red[192 + ii]; t2 += red[384 + ii]; t3 += red[576 + ii]; t4 += red[768 + ii];
        }
        atomicAdd(&g_stats[144 + co], (double)t0);
        atomicAdd(&g_stats[156 + co], (double)t1);
        atomicAdd(&g_stats[168 + co], (double)t2);
        atomicAdd(&g_stats[180 + co], (double)t3);
        atomicAdd(&g_stats[192 + co], (double)t4);
    }
}

// ---------------- bn3 + abn analytic finalize -> ca,cb,cc ----------------
__global__ void fin3_kernel(const float* __restrict__ g3, const float* __restrict__ b3,
                            const float* __restrict__ ga, const float* __restrict__ ba) {
    int c = threadIdx.x;
    if (c < HEADS) {
        double m3 = g_stats[144 + c] / CNT, e3 = g_stats[156 + c] / CNT;
        double v3 = e3 - m3 * m3;
        double alpha = (double)g3[c] / sqrt(v3 + 1e-5);
        double beta = (double)b3[c] - m3 * alpha;
        double m0 = g_stats[168 + c] / CNT, e0 = g_stats[180 + c] / CNT, ex = g_stats[192 + c] / CNT;
        double mf = alpha * m3 + beta + m0;
        double ef = alpha * alpha * e3 + beta * beta + e0
                  + 2.0 * alpha * beta * m3 + 2.0 * alpha * ex + 2.0 * beta * m0;
        double vf = ef - mf * mf;
        double sf = (double)ga[c] / sqrt(vf + 1e-5);
        g_abc[c] = (float)(sf * alpha);
        g_abc[12 + c] = (float)sf;
        g_abc[24 + c] = (float)(sf * (beta - mf) + (double)ba[c]);
    }
}

// ---------------- AV: finalize attn (-> d_out attn), out = attn @ v ------
__global__ __launch_bounds__(256) void av_kernel(float* __restrict__ out_attn) {
    int bh = blockIdx.x;
    int b = bh / HEADS, h = bh - b * HEADS;
    __shared__ float Vs[NTOK * 32];
    __shared__ float rowbuf[8][208];
    int tid = threadIdx.x;
    size_t vbase = (size_t)bh * NTOK * HD;
    for (int idx = tid; idx < NTOK * HD; idx += 256) Vs[idx] = g_v[vbase + idx];
    float ca = g_abc[h], cb = g_abc[12 + h], cc = g_abc[24 + h];
    size_t abase = (size_t)bh * HW;
    int w = tid >> 5, lane = tid & 31;
    __syncthreads();
    for (int n = w; n < NTOK; n += 8) {
        size_t rbase = abase + (size_t)n * NTOK;
#pragma unroll
        for (int cch = 0; cch < 7; cch++) {
            int m = lane + cch * 32;
            if (m < NTOK) {
                float af = ca * g_a3[rbase + m] + cb * g_attn0[rbase + m] + cc;
                rowbuf[w][m] = af;
                out_attn[rbase + m] = af;
            }
        }
        __syncwarp();
        float acc = 0.f;
#pragma unroll 4
        for (int m = 0; m < NTOK; m++) acc = fmaf(rowbuf[w][m], Vs[m * 32 + lane], acc);
        g_attnout[((size_t)(b * NTOK + n)) * DIM + h * HD + lane] = acc;
        __syncwarp();
    }
}

// ---------------- launch ----------------
extern "C" void kernel_launch(void* const* d_in, const int* in_sizes, int n_in,
                              void* d_out, int out_size) {
    const float* x        = (const float*)d_in[0];
    const float* ln1_g    = (const float*)d_in[1];
    const float* ln1_b    = (const float*)d_in[2];
    const float* qkv_w    = (const float*)d_in[3];
    const float* conv_exp = (const float*)d_in[4];
    const float* bn1_g    = (const float*)d_in[5];
    const float* bn1_b    = (const float*)d_in[6];
    const float* dw_w     = (const float*)d_in[7];
    const float* bn2_g    = (const float*)d_in[8];
    const float* bn2_b    = (const float*)d_in[9];
    const float* conv_pro = (const float*)d_in[10];
    const float* bn3_g    = (const float*)d_in[11];
    const float* bn3_b    = (const float*)d_in[12];
    const float* abn_g    = (const float*)d_in[13];
    const float* abn_b    = (const float*)d_in[14];
    const float* proj_w   = (const float*)d_in[15];
    const float* proj_b   = (const float*)d_in[16];
    const float* ln2_g    = (const float*)d_in[17];
    const float* ln2_b    = (const float*)d_in[18];
    const float* fc1_w    = (const float*)d_in[19];
    const float* fc1_b    = (const float*)d_in[20];
    const float* fc2_w    = (const float*)d_in[21];
    const float* fc2_b    = (const float*)d_in[22];
    const float* scale_ch = (const float*)d_in[23];

    float* out_x = (float*)d_out;
    float* out_attn = out_x + (size_t)MTOK * DIM;

    zero_stats_kernel<<<1, 256>>>();
    ln_kernel<<<MTOK, 128>>>(x, ln1_g, ln1_b, 0);
    gemm_kernel<1><<<dim3(1152 / 64, 99), 256>>>(qkv_w, nullptr, MTOK, 1152, DIM, nullptr, nullptr, nullptr);
    qk_softmax_kernel<<<BH, 256>>>();
    expand_kernel<<<dim3(BATCH, 8), 288>>>(conv_exp);
    bn_fin_kernel<<<1, 64>>>(bn1_g, bn1_b, 0, 36, 0);
    dw_kernel<<<dim3(BHID, 13), 256>>>(dw_w);
    bn_fin_kernel<<<1, 64>>>(bn2_g, bn2_b, 72, 108, 1);
    project_kernel<<<dim3(BATCH, 8), 192>>>(conv_pro);
    fin3_kernel<<<1, 32>>>(bn3_g, bn3_b, abn_g, abn_b);
    av_kernel<<<BH, 256>>>(out_attn);
    gemm_kernel<2><<<dim3(DIM / 64, 99), 256>>>(proj_w, nullptr, MTOK, DIM, DIM, proj_b, x, nullptr);
    ln_kernel<<<MTOK, 128>>>(nullptr, ln2_g, ln2_b, 1);
    gemm_kernel<3><<<dim3(MLPH / 64, 99), 256>>>(fc1_w, nullptr, MTOK, MLPH, DIM, fc1_b, nullptr, nullptr);
    gemm_kernel<4><<<dim3(DIM / 64, 99), 256>>>(fc2_w, out_x, MTOK, DIM, MLPH, fc2_b, nullptr, scale_ch);
}

// round 7
// speedup vs baseline: 1.8333x; 1.8333x over previous
#include <cuda_runtime.h>
#include <math.h>
#include <stdint.h>

#define BATCH 32
#define NTOK 197
#define DIM 384
#define HEADS 12
#define HD 32
#define HID 36
#define MLPH 1536
#define MTOK (BATCH*NTOK)           // 6304
#define HW (NTOK*NTOK)              // 38809
#define BH (BATCH*HEADS)            // 384
#define BHID (BATCH*HID)            // 1152
#define CNT ((double)(BATCH)*(double)HW)  // 1241888
#define EPSF 1e-5f
#define SQF 0.4204482076268573f     // 32^-0.25

// ---------------- scratch (device globals; no allocation allowed) ----------
__device__ float g_h[MTOK*DIM];
__device__ float g_q[BH*NTOK*HD];
__device__ float g_k[BH*NTOK*HD];
__device__ float g_v[BH*NTOK*HD];
__device__ float g_attn0[(size_t)BH*HW];
__device__ float g_a1[(size_t)BHID*HW];
__device__ float g_a2[(size_t)BHID*HW];
__device__ float g_a3[(size_t)BH*HW];
__device__ float g_attnout[MTOK*DIM];
__device__ float g_x1[MTOK*DIM];
__device__ float g_h2[MTOK*DIM];
__device__ float g_mlp[(size_t)MTOK*MLPH];
__device__ double g_stats[204];
__device__ float g_par1[72];
__device__ float g_par2[72];
__device__ float g_abc[36];

__device__ __forceinline__ uint32_t f2tf32(float f) {
    uint32_t r;
    asm("cvt.rna.tf32.f32 %0, %1;" : "=r"(r) : "f"(f));
    return r;
}

__device__ __forceinline__ void mma_tf32(float* c, const uint32_t* a, const uint32_t* b) {
    asm volatile(
        "mma.sync.aligned.m16n8k8.row.col.f32.tf32.tf32.f32 "
        "{%0,%1,%2,%3},{%4,%5,%6,%7},{%8,%9},{%0,%1,%2,%3};"
        : "+f"(c[0]), "+f"(c[1]), "+f"(c[2]), "+f"(c[3])
        : "r"(a[0]), "r"(a[1]), "r"(a[2]), "r"(a[3]), "r"(b[0]), "r"(b[1]));
}

// =============== mma.sync TF32 GEMM: C[m,n] = sum_k A[m,k]*W[n,k] ==========
// 128x128 tile, BK=16, 256 threads (8 warps 2x4, each 64x32), m16n8k8 frags.
// EPI 1: A=g_h      -> scatter q/k/v (*SQF on q,k)
// EPI 2: A=g_attnout-> g_x1 = resid + 2*(acc+bias)
// EPI 3: A=g_h2     -> g_mlp = gelu(acc+bias)
// EPI 4: A=g_mlp    -> Cout = g_x1 + 2*(acc+bias)*scalev
#define PADW 20

template <int EPI>
__global__ __launch_bounds__(256) void gemm_mma(const float* __restrict__ W,
                                                float* __restrict__ Cout,
                                                int M, int Nc, int K,
                                                const float* __restrict__ bias,
                                                const float* __restrict__ resid,
                                                const float* __restrict__ scalev) {
    const float* A = (EPI == 1) ? g_h : (EPI == 2) ? g_attnout : (EPI == 3) ? g_h2 : g_mlp;
    __shared__ uint32_t As[128][PADW];
    __shared__ uint32_t Ws[128][PADW];
    int tid = threadIdx.x;
    int wid = tid >> 5, lane = tid & 31;
    int g = lane >> 2, tg = lane & 3;
    int wm = (wid >> 2) * 64;   // warp row offset (2 rows)
    int wn = (wid & 3) * 32;    // warp col offset (4 cols)
    int m0 = blockIdx.y * 128, n0 = blockIdx.x * 128;

    float acc[4][4][4];
#pragma unroll
    for (int i = 0; i < 4; i++)
#pragma unroll
        for (int j = 0; j < 4; j++)
#pragma unroll
            for (int r = 0; r < 4; r++) acc[i][j][r] = 0.f;

    for (int k0 = 0; k0 < K; k0 += 16) {
#pragma unroll
        for (int it = 0; it < 2; it++) {
            int idx = tid + it * 256;
            int r = idx >> 2, c4 = (idx & 3) * 4;
            float4 va = make_float4(0.f, 0.f, 0.f, 0.f);
            if (m0 + r < M) va = *reinterpret_cast<const float4*>(A + (size_t)(m0 + r) * K + k0 + c4);
            As[r][c4 + 0] = f2tf32(va.x);
            As[r][c4 + 1] = f2tf32(va.y);
            As[r][c4 + 2] = f2tf32(va.z);
            As[r][c4 + 3] = f2tf32(va.w);
            float4 vb = *reinterpret_cast<const float4*>(W + (size_t)(n0 + r) * K + k0 + c4);
            Ws[r][c4 + 0] = f2tf32(vb.x);
            Ws[r][c4 + 1] = f2tf32(vb.y);
            Ws[r][c4 + 2] = f2tf32(vb.z);
            Ws[r][c4 + 3] = f2tf32(vb.w);
        }
        __syncthreads();
#pragma unroll
        for (int ks = 0; ks < 16; ks += 8) {
            uint32_t af[4][4];
#pragma unroll
            for (int i = 0; i < 4; i++) {
                int mr = wm + i * 16 + g;
                af[i][0] = As[mr][ks + tg];
                af[i][1] = As[mr + 8][ks + tg];
                af[i][2] = As[mr][ks + tg + 4];
                af[i][3] = As[mr + 8][ks + tg + 4];
            }
            uint32_t bf[4][2];
#pragma unroll
            for (int j = 0; j < 4; j++) {
                int nr = wn + j * 8 + g;
                bf[j][0] = Ws[nr][ks + tg];
                bf[j][1] = Ws[nr][ks + tg + 4];
            }
#pragma unroll
            for (int i = 0; i < 4; i++)
#pragma unroll
                for (int j = 0; j < 4; j++) mma_tf32(acc[i][j], af[i], bf[j]);
        }
        __syncthreads();
    }

    // epilogue: c0@(m,ne) c1@(m,ne+1) c2@(m+8,ne) c3@(m+8,ne+1)
#pragma unroll
    for (int i = 0; i < 4; i++) {
#pragma unroll
        for (int j = 0; j < 4; j++) {
#pragma unroll
            for (int half = 0; half < 2; half++) {
                int m = m0 + wm + i * 16 + g + half * 8;
                if (m >= M) continue;
#pragma unroll
                for (int cc = 0; cc < 2; cc++) {
                    int n = n0 + wn + j * 8 + 2 * tg + cc;
                    float v = acc[i][j][half * 2 + cc];
                    if (EPI == 1) {
                        int b_ = m / NTOK, tok = m - b_ * NTOK;
                        int s = n / DIM, rem = n - s * DIM;
                        int h = rem >> 5, d = rem & 31;
                        float val = v * ((s < 2) ? SQF : 1.f);
                        float* dst = (s == 0) ? g_q : (s == 1) ? g_k : g_v;
                        dst[(((size_t)(b_ * HEADS + h) * NTOK) + tok) * HD + d] = val;
                    } else if (EPI == 2) {
                        size_t idx = (size_t)m * DIM + n;
                        g_x1[idx] = resid[idx] + 2.f * (v + bias[n]);
                    } else if (EPI == 3) {
                        float t = v + bias[n];
                        g_mlp[(size_t)m * MLPH + n] = t * 0.5f * (1.f + erff(t * 0.70710678118654752f));
                    } else {
                        size_t idx = (size_t)m * DIM + n;
                        Cout[idx] = g_x1[idx] + 2.f * (v + bias[n]) * scalev[n];
                    }
                }
            }
        }
    }
}

// ---------------- zero stats ----------------
__global__ void zero_stats_kernel() {
    int t = threadIdx.x;
    if (t < 204) g_stats[t] = 0.0;
}

// ---------------- layernorm(x*0.5) ----------------
__global__ __launch_bounds__(128) void ln_kernel(const float* __restrict__ src_in,
                                                 const float* __restrict__ g,
                                                 const float* __restrict__ b,
                                                 int sel) {
    const float* src = sel ? g_x1 : src_in;
    float* dst = sel ? g_h2 : g_h;
    int tok = blockIdx.x;
    const float* xp = src + (size_t)tok * DIM;
    float* yp = dst + (size_t)tok * DIM;
    int tid = threadIdx.x;
    float v[3];
    float s = 0.f, ss = 0.f;
#pragma unroll
    for (int i = 0; i < 3; i++) {
        float t = 0.5f * xp[tid + i * 128];
        v[i] = t; s += t; ss += t * t;
    }
    __shared__ float rs[4], rss[4];
#pragma unroll
    for (int off = 16; off; off >>= 1) {
        s  += __shfl_xor_sync(0xffffffffu, s, off);
        ss += __shfl_xor_sync(0xffffffffu, ss, off);
    }
    int w = tid >> 5, lane = tid & 31;
    if (lane == 0) { rs[w] = s; rss[w] = ss; }
    __syncthreads();
    float S = rs[0] + rs[1] + rs[2] + rs[3];
    float SS = rss[0] + rss[1] + rss[2] + rss[3];
    float mean = S * (1.0f / DIM);
    float var = SS * (1.0f / DIM) - mean * mean;
    float inv = rsqrtf(var + EPSF);
#pragma unroll
    for (int i = 0; i < 3; i++) {
        int j = tid + i * 128;
        yp[j] = (v[i] - mean) * inv * g[j] + b[j];
    }
}

// ---------------- QK^T + softmax, per (b,h) ----------------
__global__ __launch_bounds__(256) void qk_softmax_kernel() {
    int bh = blockIdx.x;
    __shared__ float Ks[NTOK * 33];
    __shared__ float Qs[8][32];
    int tid = threadIdx.x;
    size_t kbase = (size_t)bh * NTOK * HD;
    for (int idx = tid; idx < NTOK * HD; idx += 256) {
        int m = idx >> 5, d = idx & 31;
        Ks[m * 33 + d] = g_k[kbase + idx];
    }
    __syncthreads();
    int w = tid >> 5, lane = tid & 31;
    for (int n = w; n < NTOK; n += 8) {
        Qs[w][lane] = g_q[kbase + (size_t)n * HD + lane];
        __syncwarp();
        float l[7];
        float mx = -1e30f;
#pragma unroll
        for (int c = 0; c < 7; c++) {
            int m = lane + c * 32;
            float a = -1e30f;
            if (m < NTOK) {
                a = 0.f;
#pragma unroll
                for (int d = 0; d < 32; d++) a = fmaf(Qs[w][d], Ks[m * 33 + d], a);
            }
            l[c] = a;
            mx = fmaxf(mx, a);
        }
#pragma unroll
        for (int off = 16; off; off >>= 1) mx = fmaxf(mx, __shfl_xor_sync(0xffffffffu, mx, off));
        float sum = 0.f;
#pragma unroll
        for (int c = 0; c < 7; c++) {
            l[c] = __expf(l[c] - mx);
            sum += l[c];
        }
#pragma unroll
        for (int off = 16; off; off >>= 1) sum += __shfl_xor_sync(0xffffffffu, sum, off);
        float inv = 1.f / sum;
        size_t obase = (size_t)bh * HW + (size_t)n * NTOK;
#pragma unroll
        for (int c = 0; c < 7; c++) {
            int m = lane + c * 32;
            if (m < NTOK) g_attn0[obase + m] = l[c] * inv;
        }
        __syncwarp();
    }
}

// ---------------- expand 1x1 + bn1 moments ----------------
__global__ __launch_bounds__(288) void expand_kernel(const float* __restrict__ wexp) {
    int b = blockIdx.x;
    int grp = blockIdx.y;
    int tid = threadIdx.x;
    int co = tid >> 3, j = tid & 7;
    float w[12];
#pragma unroll
    for (int i = 0; i < 12; i++) w[i] = wexp[co * 12 + i];
    __shared__ float insm[12 * 512];
    __shared__ float reds[288], redss[288];
    float s = 0.f, ss = 0.f;
    for (int tt = grp; tt < 76; tt += 8) {
        int hw0 = tt * 512;
        __syncthreads();
        for (int idx = tid; idx < 12 * 512; idx += 288) {
            int ci = idx >> 9, p = idx & 511;
            int hw = hw0 + p;
            insm[idx] = (hw < HW) ? g_attn0[(size_t)(b * HEADS + ci) * HW + hw] : 0.f;
        }
        __syncthreads();
        for (int p = j; p < 512; p += 8) {
            int hw = hw0 + p;
            if (hw < HW) {
                float acc = 0.f;
#pragma unroll
                for (int i = 0; i < 12; i++) acc = fmaf(w[i], insm[i * 512 + p], acc);
                g_a1[(size_t)(b * HID + co) * HW + hw] = acc;
                s += acc; ss += acc * acc;
            }
        }
    }
    reds[tid] = s; redss[tid] = ss;
    __syncthreads();
    if (j == 0) {
        float ts = 0.f, tss = 0.f;
#pragma unroll
        for (int q = 0; q < 8; q++) { ts += reds[co * 8 + q]; tss += redss[co * 8 + q]; }
        atomicAdd(&g_stats[co], (double)ts);
        atomicAdd(&g_stats[36 + co], (double)tss);
    }
}

// ---------------- bn finalize (bn1/bn2) ----------------
__global__ void bn_fin_kernel(const float* __restrict__ g, const float* __restrict__ b,
                              int soff, int ssoff, int which) {
    int c = threadIdx.x;
    if (c < HID) {
        double mean = g_stats[soff + c] / CNT;
        double var = g_stats[ssoff + c] / CNT - mean * mean;
        double sc = (double)g[c] / sqrt(var + 1e-5);
        float* par = which ? g_par2 : g_par1;
        par[c] = (float)sc;
        par[36 + c] = (float)((double)b[c] - mean * sc);
    }
}

// ---------------- depthwise 3x3 + bn2 moments ----------------
__global__ __launch_bounds__(256) void dw_kernel(const float* __restrict__ dww) {
    int bc = blockIdx.x;
    int b = bc / HID, c = bc - b * HID;
    int y0 = blockIdx.y * 16;
    float sc = g_par1[c], sh = g_par1[36 + c];
    float w9[9];
#pragma unroll
    for (int i = 0; i < 9; i++) w9[i] = dww[c * 9 + i];
    __shared__ float sm[18 * NTOK];
    int tid = threadIdx.x;
    const float* src = g_a1 + (size_t)bc * HW;
    for (int idx = tid; idx < 18 * NTOK; idx += 256) {
        int r = idx / NTOK, xcol = idx - r * NTOK;
        int y = y0 - 1 + r;
        float v = 0.f;
        if (y >= 0 && y < NTOK) {
            v = src[(size_t)y * NTOK + xcol] * sc + sh;
            v = fminf(fmaxf(v, 0.f), 6.f);
        }
        sm[idx] = v;
    }
    __syncthreads();
    float s = 0.f, ss = 0.f;
    float* dst = g_a2 + (size_t)bc * HW;
    for (int idx = tid; idx < 16 * NTOK; idx += 256) {
        int yy = idx / NTOK, xcol = idx - yy * NTOK;
        int y = y0 + yy;
        if (y < NTOK) {
            float acc = 0.f;
#pragma unroll
            for (int ky = 0; ky < 3; ky++) {
                const float* row = sm + (yy + ky) * NTOK;
                if (xcol > 0) acc = fmaf(w9[ky * 3 + 0], row[xcol - 1], acc);
                acc = fmaf(w9[ky * 3 + 1], row[xcol], acc);
                if (xcol < NTOK - 1) acc = fmaf(w9[ky * 3 + 2], row[xcol + 1], acc);
            }
            dst[(size_t)y * NTOK + xcol] = acc;
            s += acc; ss += acc * acc;
        }
    }
    __shared__ float rs[8], rss[8];
#pragma unroll
    for (int off = 16; off; off >>= 1) {
        s  += __shfl_xor_sync(0xffffffffu, s, off);
        ss += __shfl_xor_sync(0xffffffffu, ss, off);
    }
    int w = tid >> 5, lane = tid & 31;
    if (lane == 0) { rs[w] = s; rss[w] = ss; }
    __syncthreads();
    if (tid == 0) {
        float ts = 0.f, tss = 0.f;
#pragma unroll
        for (int q = 0; q < 8; q++) { ts += rs[q]; tss += rss[q]; }
        atomicAdd(&g_stats[72 + c], (double)ts);
        atomicAdd(&g_stats[108 + c], (double)tss);
    }
}

// ---------------- project 1x1 + 5 moments ----------------
__global__ __launch_bounds__(192) void project_kernel(const float* __restrict__ wpro) {
    int b = blockIdx.x;
    int grp = blockIdx.y;
    int tid = threadIdx.x;
    int co = tid >> 4, j = tid & 15;
    float w[36];
#pragma unroll
    for (int i = 0; i < 36; i++) w[i] = wpro[co * 36 + i];
    __shared__ float insm[36 * 256];
    __shared__ float red[192 * 5];
    float s3 = 0.f, ss3 = 0.f, s0 = 0.f, ss0 = 0.f, sx = 0.f;
    for (int tt = grp; tt < 152; tt += 8) {
        int hw0 = tt * 256;
        __syncthreads();
        for (int idx = tid; idx < 36 * 256; idx += 192) {
            int ci = idx >> 8, p = idx & 255;
            int hw = hw0 + p;
            float v = 0.f;
            if (hw < HW) {
                v = g_a2[(size_t)(b * HID + ci) * HW + hw] * g_par2[ci] + g_par2[36 + ci];
                v = fminf(fmaxf(v, 0.f), 6.f);
            }
            insm[idx] = v;
        }
        __syncthreads();
        for (int p = j; p < 256; p += 16) {
            int hw = hw0 + p;
            if (hw < HW) {
                float acc = 0.f;
#pragma unroll
                for (int i = 0; i < 36; i++) acc = fmaf(w[i], insm[i * 256 + p], acc);
                size_t oidx = (size_t)(b * HEADS + co) * HW + hw;
                g_a3[oidx] = acc;
                float a0 = g_attn0[oidx];
                s3 += acc; ss3 += acc * acc;
                s0 += a0;  ss0 += a0 * a0;
                sx += acc * a0;
            }
        }
    }
    red[tid] = s3; red[192 + tid] = ss3; red[384 + tid] = s0; red[576 + tid] = ss0; red[768 + tid] = sx;
    __syncthreads();
    if (j == 0) {
        float t0 = 0.f, t1 = 0.f, t2 = 0.f, t3 = 0.f, t4 = 0.f;
#pragma unroll
        for (int q = 0; q < 16; q++) {
            int ii = co * 16 + q;
            t0 += red[ii]; t1 += red[192 + ii]; t2 += red[384 + ii]; t3 += red[576 + ii]; t4 += red[768 + ii];
        }
        atomicAdd(&g_stats[144 + co], (double)t0);
        atomicAdd(&g_stats[156 + co], (double)t1);
        atomicAdd(&g_stats[168 + co], (double)t2);
        atomicAdd(&g_stats[180 + co], (double)t3);
        atomicAdd(&g_stats[192 + co], (double)t4);
    }
}

// ---------------- bn3 + abn analytic finalize ----------------
__global__ void fin3_kernel(const float* __restrict__ g3, const float* __restrict__ b3,
                            const float* __restrict__ ga, const float* __restrict__ ba) {
    int c = threadIdx.x;
    if (c < HEADS) {
        double m3 = g_stats[144 + c] / CNT, e3 = g_stats[156 + c] / CNT;
        double v3 = e3 - m3 * m3;
        double alpha = (double)g3[c] / sqrt(v3 + 1e-5);
        double beta = (double)b3[c] - m3 * alpha;
        double m0 = g_stats[168 + c] / CNT, e0 = g_stats[180 + c] / CNT, ex = g_stats[192 + c] / CNT;
        double mf = alpha * m3 + beta + m0;
        double ef = alpha * alpha * e3 + beta * beta + e0
                  + 2.0 * alpha * beta * m3 + 2.0 * alpha * ex + 2.0 * beta * m0;
        double vf = ef - mf * mf;
        double sf = (double)ga[c] / sqrt(vf + 1e-5);
        g_abc[c] = (float)(sf * alpha);
        g_abc[12 + c] = (float)sf;
        g_abc[24 + c] = (float)(sf * (beta - mf) + (double)ba[c]);
    }
}

// ---------------- AV: finalize attn + A@V ----------------
__global__ __launch_bounds__(256) void av_kernel(float* __restrict__ out_attn) {
    int bh = blockIdx.x;
    int b = bh / HEADS, h = bh - b * HEADS;
    __shared__ float Vs[NTOK * 32];
    __shared__ float rowbuf[8][208];
    int tid = threadIdx.x;
    size_t vbase = (size_t)bh * NTOK * HD;
    for (int idx = tid; idx < NTOK * HD; idx += 256) Vs[idx] = g_v[vbase + idx];
    float ca = g_abc[h], cb = g_abc[12 + h], cc = g_abc[24 + h];
    size_t abase = (size_t)bh * HW;
    int w = tid >> 5, lane = tid & 31;
    __syncthreads();
    for (int n = w; n < NTOK; n += 8) {
        size_t rbase = abase + (size_t)n * NTOK;
#pragma unroll
        for (int cch = 0; cch < 7; cch++) {
            int m = lane + cch * 32;
            if (m < NTOK) {
                float af = ca * g_a3[rbase + m] + cb * g_attn0[rbase + m] + cc;
                rowbuf[w][m] = af;
                out_attn[rbase + m] = af;
            }
        }
        __syncwarp();
        float acc = 0.f;
#pragma unroll 4
        for (int m = 0; m < NTOK; m++) acc = fmaf(rowbuf[w][m], Vs[m * 32 + lane], acc);
        g_attnout[((size_t)(b * NTOK + n)) * DIM + h * HD + lane] = acc;
        __syncwarp();
    }
}

// ---------------- launch ----------------
extern "C" void kernel_launch(void* const* d_in, const int* in_sizes, int n_in,
                              void* d_out, int out_size) {
    const float* x        = (const float*)d_in[0];
    const float* ln1_g    = (const float*)d_in[1];
    const float* ln1_b    = (const float*)d_in[2];
    const float* qkv_w    = (const float*)d_in[3];
    const float* conv_exp = (const float*)d_in[4];
    const float* bn1_g    = (const float*)d_in[5];
    const float* bn1_b    = (const float*)d_in[6];
    const float* dw_w     = (const float*)d_in[7];
    const float* bn2_g    = (const float*)d_in[8];
    const float* bn2_b    = (const float*)d_in[9];
    const float* conv_pro = (const float*)d_in[10];
    const float* bn3_g    = (const float*)d_in[11];
    const float* bn3_b    = (const float*)d_in[12];
    const float* abn_g    = (const float*)d_in[13];
    const float* abn_b    = (const float*)d_in[14];
    const float* proj_w   = (const float*)d_in[15];
    const float* proj_b   = (const float*)d_in[16];
    const float* ln2_g    = (const float*)d_in[17];
    const float* ln2_b    = (const float*)d_in[18];
    const float* fc1_w    = (const float*)d_in[19];
    const float* fc1_b    = (const float*)d_in[20];
    const float* fc2_w    = (const float*)d_in[21];
    const float* fc2_b    = (const float*)d_in[22];
    const float* scale_ch = (const float*)d_in[23];

    float* out_x = (float*)d_out;
    float* out_attn = out_x + (size_t)MTOK * DIM;

    int mtiles = (MTOK + 127) / 128;  // 50

    zero_stats_kernel<<<1, 256>>>();
    ln_kernel<<<MTOK, 128>>>(x, ln1_g, ln1_b, 0);
    gemm_mma<1><<<dim3(1152 / 128, mtiles), 256>>>(qkv_w, nullptr, MTOK, 1152, DIM, nullptr, nullptr, nullptr);
    qk_softmax_kernel<<<BH, 256>>>();
    expand_kernel<<<dim3(BATCH, 8), 288>>>(conv_exp);
    bn_fin_kernel<<<1, 64>>>(bn1_g, bn1_b, 0, 36, 0);
    dw_kernel<<<dim3(BHID, 13), 256>>>(dw_w);
    bn_fin_kernel<<<1, 64>>>(bn2_g, bn2_b, 72, 108, 1);
    project_kernel<<<dim3(BATCH, 8), 192>>>(conv_pro);
    fin3_kernel<<<1, 32>>>(bn3_g, bn3_b, abn_g, abn_b);
    av_kernel<<<BH, 256>>>(out_attn);
    gemm_mma<2><<<dim3(DIM / 128, mtiles), 256>>>(proj_w, nullptr, MTOK, DIM, DIM, proj_b, x, nullptr);
    ln_kernel<<<MTOK, 128>>>(nullptr, ln2_g, ln2_b, 1);
    gemm_mma<3><<<dim3(MLPH / 128, mtiles), 256>>>(fc1_w, nullptr, MTOK, MLPH, DIM, fc1_b, nullptr, nullptr);
    gemm_mma<4><<<dim3(DIM / 128, mtiles), 256>>>(fc2_w, out_x, MTOK, DIM, MLPH, fc2_b, nullptr, scale_ch);
}